// round 2
// baseline (speedup 1.0000x reference)
#include <cuda_runtime.h>
#include <cuda_bf16.h>

// out[i] = w_node * nodes[i, 0] + b_node   (pre-seeds the accumulator)
__global__ void tmp_init_kernel(const float* __restrict__ nodes,
                                const float* __restrict__ w_node_p,
                                const float* __restrict__ b_node_p,
                                float* __restrict__ out,
                                int n_nodes, int d_node) {
    int i = blockIdx.x * blockDim.x + threadIdx.x;
    if (i < n_nodes) {
        float wn = __ldg(w_node_p);
        float bn = __ldg(b_node_p);
        out[i] = wn * __ldg(nodes + (size_t)i * d_node) + bn;
    }
}

// 8 edges per thread. All loads issued up front (high MLP), streaming hints
// on the one-touch data, then 8 fire-and-forget atomic adds.
__global__ __launch_bounds__(256)
void tmp_edge_kernel(const float* __restrict__ nodes,
                     const float* __restrict__ edges,
                     const int*   __restrict__ senders,
                     const int*   __restrict__ receivers,
                     const float* __restrict__ w_node_p,
                     const float* __restrict__ w_edge_p,
                     float* __restrict__ out,
                     int n_edges, int d_node, int d_edge) {
    const float wn = __ldg(w_node_p);
    const float we = __ldg(w_edge_p);

    int tid  = blockIdx.x * blockDim.x + threadIdx.x;
    int base = tid * 8;

    if (base + 7 < n_edges) {
        // Vectorized, streaming index loads (evict-first: one-touch data).
        int4 sa = __ldcs((const int4*)(senders)   + tid * 2);
        int4 sb = __ldcs((const int4*)(senders)   + tid * 2 + 1);
        int4 ra = __ldcs((const int4*)(receivers) + tid * 2);
        int4 rb = __ldcs((const int4*)(receivers) + tid * 2 + 1);

        // Edge values: one 64B line each, streaming.
        float e0 = __ldcs(edges + (size_t)(base + 0) * d_edge);
        float e1 = __ldcs(edges + (size_t)(base + 1) * d_edge);
        float e2 = __ldcs(edges + (size_t)(base + 2) * d_edge);
        float e3 = __ldcs(edges + (size_t)(base + 3) * d_edge);
        float e4 = __ldcs(edges + (size_t)(base + 4) * d_edge);
        float e5 = __ldcs(edges + (size_t)(base + 5) * d_edge);
        float e6 = __ldcs(edges + (size_t)(base + 6) * d_edge);
        float e7 = __ldcs(edges + (size_t)(base + 7) * d_edge);

        // Node gathers: small L2-resident footprint, default caching.
        float n0 = __ldg(nodes + (size_t)sa.x * d_node);
        float n1 = __ldg(nodes + (size_t)sa.y * d_node);
        float n2 = __ldg(nodes + (size_t)sa.z * d_node);
        float n3 = __ldg(nodes + (size_t)sa.w * d_node);
        float n4 = __ldg(nodes + (size_t)sb.x * d_node);
        float n5 = __ldg(nodes + (size_t)sb.y * d_node);
        float n6 = __ldg(nodes + (size_t)sb.z * d_node);
        float n7 = __ldg(nodes + (size_t)sb.w * d_node);

        atomicAdd(out + ra.x, fmaf(we, e0, wn * n0));
        atomicAdd(out + ra.y, fmaf(we, e1, wn * n1));
        atomicAdd(out + ra.z, fmaf(we, e2, wn * n2));
        atomicAdd(out + ra.w, fmaf(we, e3, wn * n3));
        atomicAdd(out + rb.x, fmaf(we, e4, wn * n4));
        atomicAdd(out + rb.y, fmaf(we, e5, wn * n5));
        atomicAdd(out + rb.z, fmaf(we, e6, wn * n6));
        atomicAdd(out + rb.w, fmaf(we, e7, wn * n7));
    } else {
        // Tail path
        for (int e = base; e < n_edges; ++e) {
            int s = __ldg(senders + e);
            int r = __ldg(receivers + e);
            float ev = __ldg(edges + (size_t)e * d_edge);
            float nv = __ldg(nodes + (size_t)s * d_node);
            atomicAdd(out + r, fmaf(we, ev, wn * nv));
        }
    }
}

extern "C" void kernel_launch(void* const* d_in, const int* in_sizes, int n_in,
                              void* d_out, int out_size) {
    const float* nodes     = (const float*)d_in[0];
    const float* edges     = (const float*)d_in[1];
    const int*   senders   = (const int*)  d_in[2];
    const int*   receivers = (const int*)  d_in[3];
    const float* w_node    = (const float*)d_in[4];
    const float* w_edge    = (const float*)d_in[5];
    const float* b_node    = (const float*)d_in[6];
    float*       out       = (float*)d_out;

    const int n_nodes = out_size;
    const int n_edges = in_sizes[2];
    const int d_node  = in_sizes[0] / n_nodes;   // 128
    const int d_edge  = in_sizes[1] / n_edges;   // 16

    // 1) Seed output with w_node*nodes[:,0] + b_node
    {
        int threads = 256;
        int blocks  = (n_nodes + threads - 1) / threads;
        tmp_init_kernel<<<blocks, threads>>>(nodes, w_node, b_node, out, n_nodes, d_node);
    }

    // 2) Scatter-add messages (8 edges per thread)
    {
        int threads = 256;
        int edges_per_block = threads * 8;
        int blocks = (n_edges + edges_per_block - 1) / edges_per_block;
        tmp_edge_kernel<<<blocks, threads>>>(nodes, edges, senders, receivers,
                                             w_node, w_edge, out,
                                             n_edges, d_node, d_edge);
    }
}

// round 3
// speedup vs baseline: 1.1678x; 1.1678x over previous
#include <cuda_runtime.h>
#include <cuda_bf16.h>

// out[i] = w_node * nodes[i, 0] + b_node   (pre-seeds the accumulator)
__global__ void tmp_init_kernel(const float* __restrict__ nodes,
                                const float* __restrict__ w_node_p,
                                const float* __restrict__ b_node_p,
                                float* __restrict__ out,
                                int n_nodes, int d_node) {
    int i = blockIdx.x * blockDim.x + threadIdx.x;
    if (i < n_nodes) {
        float wn = __ldg(w_node_p);
        float bn = __ldg(b_node_p);
        out[i] = wn * __ldg(nodes + (size_t)i * d_node) + bn;
    }
}

// Warp-cooperative: each warp handles 32 consecutive edges.
// The 32 edge rows (32 x 64B = 2KB) are read as 4 fully-coalesced float4
// sweeps (512B each), then element 0 of each row is redistributed via shfl
// so lane L owns edge L. Same DRAM bytes as scalar loads (controller moves
// full rows either way) but a perfectly sequential request stream.
__global__ __launch_bounds__(256)
void tmp_edge_kernel(const float* __restrict__ nodes,
                     const float* __restrict__ edges,
                     const int*   __restrict__ senders,
                     const int*   __restrict__ receivers,
                     const float* __restrict__ w_node_p,
                     const float* __restrict__ w_edge_p,
                     float* __restrict__ out,
                     int n_edges, int d_node, int d_edge) {
    const float wn = __ldg(w_node_p);
    const float we = __ldg(w_edge_p);

    const int tid         = blockIdx.x * blockDim.x + threadIdx.x;
    const int warp_global = tid >> 5;
    const int lane        = tid & 31;
    const int base        = warp_global * 32;        // first edge of this warp

    if (base >= n_edges) return;

    if (base + 32 <= n_edges && d_edge == 16) {
        // ---- Fast path ----
        // Coalesced index loads: one edge per lane.
        const int e = base + lane;
        const int s = __ldcs(senders + e);
        const int r = __ldcs(receivers + e);

        // 4 coalesced float4 sweeps over the warp's 2KB of edge rows.
        // Sweep c, lane l reads float4 index (base*4 + c*32 + l):
        //   edge = base + c*8 + l/4, component = l%4.
        // Element 0 of each edge row sits in lanes with l%4==0, component .x.
        const float4* ef4 = (const float4*)edges;
        const size_t f4base = (size_t)base * 4;
        float4 q0 = __ldcs(ef4 + f4base + 0 * 32 + lane);
        float4 q1 = __ldcs(ef4 + f4base + 1 * 32 + lane);
        float4 q2 = __ldcs(ef4 + f4base + 2 * 32 + lane);
        float4 q3 = __ldcs(ef4 + f4base + 3 * 32 + lane);

        // Gather (scattered, L2-resident footprint) — issue before shuffles.
        const float nv = __ldg(nodes + (size_t)s * d_node);

        // Redistribute: lane L wants edge base+L, which lives in sweep L/8,
        // source lane (L%8)*4, component .x.
        const int src = (lane & 7) * 4;
        float t0 = __shfl_sync(0xffffffffu, q0.x, src);
        float t1 = __shfl_sync(0xffffffffu, q1.x, src);
        float t2 = __shfl_sync(0xffffffffu, q2.x, src);
        float t3 = __shfl_sync(0xffffffffu, q3.x, src);
        const int sel = lane >> 3;                   // 0..3
        float ev = (sel == 0) ? t0 : (sel == 1) ? t1 : (sel == 2) ? t2 : t3;

        atomicAdd(out + r, fmaf(we, ev, wn * nv));
    } else {
        // ---- Tail / generic path: one edge per lane, scalar loads ----
        const int e = base + lane;
        if (e < n_edges) {
            const int s = __ldg(senders + e);
            const int r = __ldg(receivers + e);
            const float ev = __ldg(edges + (size_t)e * d_edge);
            const float nv = __ldg(nodes + (size_t)s * d_node);
            atomicAdd(out + r, fmaf(we, ev, wn * nv));
        }
    }
}

extern "C" void kernel_launch(void* const* d_in, const int* in_sizes, int n_in,
                              void* d_out, int out_size) {
    const float* nodes     = (const float*)d_in[0];
    const float* edges     = (const float*)d_in[1];
    const int*   senders   = (const int*)  d_in[2];
    const int*   receivers = (const int*)  d_in[3];
    const float* w_node    = (const float*)d_in[4];
    const float* w_edge    = (const float*)d_in[5];
    const float* b_node    = (const float*)d_in[6];
    float*       out       = (float*)d_out;

    const int n_nodes = out_size;
    const int n_edges = in_sizes[2];
    const int d_node  = in_sizes[0] / n_nodes;   // 128
    const int d_edge  = in_sizes[1] / n_edges;   // 16

    // 1) Seed output with w_node*nodes[:,0] + b_node
    {
        int threads = 256;
        int blocks  = (n_nodes + threads - 1) / threads;
        tmp_init_kernel<<<blocks, threads>>>(nodes, w_node, b_node, out, n_nodes, d_node);
    }

    // 2) Scatter-add messages (32 edges per warp, warp-cooperative)
    {
        int threads = 256;                       // 8 warps/block
        int edges_per_block = (threads / 32) * 32 * 1;  // 8 warps * 32 edges
        int blocks = (n_edges + edges_per_block * 1 - 1) / (edges_per_block);
        tmp_edge_kernel<<<blocks, threads>>>(nodes, edges, senders, receivers,
                                             w_node, w_edge, out,
                                             n_edges, d_node, d_edge);
    }
}